// round 1
// baseline (speedup 1.0000x reference)
#include <cuda_runtime.h>
#include <cuda_bf16.h>
#include <cstdint>

#define BB 64
#define SS 512
#define DD 1024
#define HH 1024
#define TT 9

// Scratch (device globals; no allocation allowed)
__device__ float4 g_Weff4[DD * 3];   // row d: [t0..t3][t4..t7][t8,0,0,0]
__device__ float  g_beff[TT];
__device__ float  g_score[BB];
__device__ float  g_logz[BB];

// ---------------------------------------------------------------------------
// Kernel 1: Weff[d,t] = sum_h W1[d,h]*W2[h,t];  beff[t] = sum_h b1[h]*W2[h,t] + b2[t]
// grid = DD+1 blocks (last block computes beff), 256 threads
// ---------------------------------------------------------------------------
__global__ __launch_bounds__(256) void weff_kernel(
    const float* __restrict__ W1, const float* __restrict__ b1,
    const float* __restrict__ W2, const float* __restrict__ b2)
{
    int d = blockIdx.x;
    float acc[TT];
#pragma unroll
    for (int t = 0; t < TT; t++) acc[t] = 0.f;

    if (d < DD) {
        const float* w1r = W1 + (size_t)d * HH;
        for (int h = threadIdx.x; h < HH; h += 256) {
            float a = w1r[h];
            const float* w2r = W2 + (size_t)h * TT;
#pragma unroll
            for (int t = 0; t < TT; t++) acc[t] = fmaf(a, w2r[t], acc[t]);
        }
    } else {
        for (int h = threadIdx.x; h < HH; h += 256) {
            float a = b1[h];
            const float* w2r = W2 + (size_t)h * TT;
#pragma unroll
            for (int t = 0; t < TT; t++) acc[t] = fmaf(a, w2r[t], acc[t]);
        }
    }

    // warp reduce
#pragma unroll
    for (int t = 0; t < TT; t++)
#pragma unroll
        for (int o = 16; o; o >>= 1)
            acc[t] += __shfl_xor_sync(0xffffffffu, acc[t], o);

    __shared__ float sred[8][TT];
    int wid = threadIdx.x >> 5, lane = threadIdx.x & 31;
    if (lane == 0) {
#pragma unroll
        for (int t = 0; t < TT; t++) sred[wid][t] = acc[t];
    }
    __syncthreads();
    if (threadIdx.x == 0) {
        float r[TT];
#pragma unroll
        for (int t = 0; t < TT; t++) {
            float s = 0.f;
#pragma unroll
            for (int w = 0; w < 8; w++) s += sred[w][t];
            r[t] = s;
        }
        if (d < DD) {
            g_Weff4[d * 3 + 0] = make_float4(r[0], r[1], r[2], r[3]);
            g_Weff4[d * 3 + 1] = make_float4(r[4], r[5], r[6], r[7]);
            g_Weff4[d * 3 + 2] = make_float4(r[8], 0.f, 0.f, 0.f);
        } else {
#pragma unroll
            for (int t = 0; t < TT; t++) g_beff[t] = r[t] + b2[t];
        }
    }
}

// ---------------------------------------------------------------------------
// Kernel 2: logits[r,t] = sum_d input[r,d] * Weff[d,t] + beff[t]
// grid = 256 blocks x 128 threads. Each thread owns one row (128 rows/block).
// Input staged via smem (stride 9 float4 -> conflict-free), Weff broadcast
// from smem (uniform address -> 1-phase broadcast). K processed in two 512
// halves (24 KB Weff smem each), chunks of 32 with register double-buffering.
// ---------------------------------------------------------------------------
__global__ __launch_bounds__(128) void gemv_kernel(
    const float* __restrict__ input, float* __restrict__ logits)
{
    __shared__ float4 sW[1536];       // 512 Weff rows * 3 float4 = 24 KB
    __shared__ float4 sIn[128 * 9];   // 128 rows * 8 float4 used, stride 9 = 18 KB

    int tid = threadIdx.x;
    int r0  = blockIdx.x * 128;
    const float4* in4 = (const float4*)input;

    float a0=0.f,a1=0.f,a2=0.f,a3=0.f,a4=0.f,a5=0.f,a6=0.f,a7=0.f,a8=0.f;

    // prefetch chunk 0
    float4 st[8];
#pragma unroll
    for (int i = 0; i < 8; i++) {
        int idx = i * 128 + tid;
        int rr = idx >> 3, c4 = idx & 7;
        st[i] = in4[(size_t)(r0 + rr) * 256 + c4];
    }

    for (int c = 0; c < 32; c++) {
        if ((c & 15) == 0) {
            __syncthreads();
            const float4* src = g_Weff4 + (c >> 4) * 1536;
#pragma unroll
            for (int k = 0; k < 12; k++) sW[k * 128 + tid] = src[k * 128 + tid];
        }
        // commit staged regs to smem
#pragma unroll
        for (int i = 0; i < 8; i++) {
            int idx = i * 128 + tid;
            int rr = idx >> 3, c4 = idx & 7;
            sIn[rr * 9 + c4] = st[i];
        }
        __syncthreads();
        // prefetch next chunk (global, overlaps compute)
        if (c < 31) {
            int k4 = (c + 1) * 8;
#pragma unroll
            for (int i = 0; i < 8; i++) {
                int idx = i * 128 + tid;
                int rr = idx >> 3, c4 = idx & 7;
                st[i] = in4[(size_t)(r0 + rr) * 256 + k4 + c4];
            }
        }
        int wbase = (c & 15) * 32;
#pragma unroll
        for (int c4 = 0; c4 < 8; c4++) {
            float4 x = sIn[tid * 9 + c4];
#pragma unroll
            for (int j = 0; j < 4; j++) {
                int wrow = wbase + c4 * 4 + j;
                float4 w0 = sW[wrow * 3 + 0];
                float4 w1 = sW[wrow * 3 + 1];
                float4 w2 = sW[wrow * 3 + 2];
                float xv = (j == 0) ? x.x : (j == 1) ? x.y : (j == 2) ? x.z : x.w;
                a0 = fmaf(xv, w0.x, a0); a1 = fmaf(xv, w0.y, a1);
                a2 = fmaf(xv, w0.z, a2); a3 = fmaf(xv, w0.w, a3);
                a4 = fmaf(xv, w1.x, a4); a5 = fmaf(xv, w1.y, a5);
                a6 = fmaf(xv, w1.z, a6); a7 = fmaf(xv, w1.w, a7);
                a8 = fmaf(xv, w2.x, a8);
            }
        }
        __syncthreads();
    }

    int row = r0 + tid;
    float* o = logits + (size_t)row * TT;
    o[0] = a0 + g_beff[0]; o[1] = a1 + g_beff[1]; o[2] = a2 + g_beff[2];
    o[3] = a3 + g_beff[3]; o[4] = a4 + g_beff[4]; o[5] = a5 + g_beff[5];
    o[6] = a6 + g_beff[6]; o[7] = a7 + g_beff[7]; o[8] = a8 + g_beff[8];
}

// ---------------------------------------------------------------------------
// Kernel 3: CRF log-partition per batch. 1 warp per batch; lanes 0..8 = tags.
// Uses precomputed exp(trans) so each step needs 1 exp + 1 log per lane:
//   M = alpha[0];  p_i = exp(a_i - M);  alpha'_j = M + log(sum_i p_i*E[i][j]) + em_j
// (trans in [-0.1,0.1] keeps alpha spread small -> M=alpha[0] is a safe shift)
// ---------------------------------------------------------------------------
__global__ __launch_bounds__(32) void crf_denom_kernel(
    const float* __restrict__ logits, const int* __restrict__ mask,
    const float* __restrict__ start, const float* __restrict__ endt,
    const float* __restrict__ trans)
{
    __shared__ float s_em[SS * TT];
    __shared__ int   s_mk[SS];

    int b = blockIdx.x, j = threadIdx.x;
    const float* em = logits + (size_t)b * SS * TT;
    for (int i = j; i < SS * TT; i += 32) s_em[i] = em[i];    // base may be misaligned: scalar loads
    const int* mk = mask + (size_t)b * SS;
    for (int i = j; i < SS; i += 32) s_mk[i] = mk[i];
    __syncwarp();

    const float NEG = -1e30f;
    bool act = (j < TT);
    float E[TT];
#pragma unroll
    for (int i = 0; i < TT; i++) E[i] = act ? __expf(trans[i * TT + j]) : 0.f;

    float alpha = act ? (start[j] + s_em[j]) : NEG;

#pragma unroll 4
    for (int t = 1; t < SS; t++) {
        float emt = act ? s_em[t * TT + j] : 0.f;
        int   m   = s_mk[t];
        float M   = __shfl_sync(0xffffffffu, alpha, 0);
        float p   = __expf(alpha - M);
        float s = 0.f;
#pragma unroll
        for (int i = 0; i < TT; i++) {
            float pi = __shfl_sync(0xffffffffu, p, i);
            s = fmaf(pi, E[i], s);
        }
        float nxt = M + __logf(s) + emt;
        if (m > 0 && act) alpha = nxt;
    }

    float v  = act ? (alpha + endt[j]) : NEG;
    float Mx = v;
#pragma unroll
    for (int o = 16; o; o >>= 1) Mx = fmaxf(Mx, __shfl_xor_sync(0xffffffffu, Mx, o));
    float e = __expf(v - Mx);
#pragma unroll
    for (int o = 16; o; o >>= 1) e += __shfl_xor_sync(0xffffffffu, e, o);
    if (j == 0) g_logz[b] = Mx + __logf(e);
}

// ---------------------------------------------------------------------------
// Kernel 4: CRF gold-path score per batch. 1 block of 512 threads per batch.
// ---------------------------------------------------------------------------
__global__ __launch_bounds__(512) void crf_num_kernel(
    const float* __restrict__ logits, const int* __restrict__ labels,
    const int* __restrict__ mask, const float* __restrict__ start,
    const float* __restrict__ endt, const float* __restrict__ trans)
{
    __shared__ int   tg[SS];
    __shared__ int   mk[SS];
    __shared__ float red[SS];
    __shared__ int   ridx[SS];

    int b = blockIdx.x, t = threadIdx.x;
    tg[t] = labels[(size_t)b * SS + t];
    mk[t] = mask[(size_t)b * SS + t];
    __syncthreads();

    const float* em = logits + (size_t)b * SS * TT;
    float c = 0.f;
    if (t == 0) {
        c = start[tg[0]] + em[tg[0]];
    } else if (mk[t] > 0) {
        int tp = t - 1;
        while (tp > 0 && mk[tp] == 0) tp--;
        c = trans[tg[tp] * TT + tg[t]] + em[(size_t)t * TT + tg[t]];
    }
    red[t]  = c;
    ridx[t] = (mk[t] > 0) ? t : 0;
    __syncthreads();
#pragma unroll
    for (int o = 256; o; o >>= 1) {
        if (t < o) {
            red[t] += red[t + o];
            ridx[t] = max(ridx[t], ridx[t + o]);
        }
        __syncthreads();
    }
    if (t == 0) g_score[b] = red[0] + endt[tg[ridx[0]]];
}

// ---------------------------------------------------------------------------
// Kernel 5: deterministic fixed-order reduce -> loss = mean(logz - score)
// ---------------------------------------------------------------------------
__global__ __launch_bounds__(64) void final_kernel(float* __restrict__ out)
{
    __shared__ float sv[BB];
    int t = threadIdx.x;
    sv[t] = g_logz[t] - g_score[t];
    __syncthreads();
#pragma unroll
    for (int o = 32; o; o >>= 1) {
        if (t < o) sv[t] += sv[t + o];
        __syncthreads();
    }
    if (t == 0) out[0] = sv[0] * (1.0f / 64.0f);
}

// ---------------------------------------------------------------------------
extern "C" void kernel_launch(void* const* d_in, const int* in_sizes, int n_in,
                              void* d_out, int out_size)
{
    const float* input  = (const float*)d_in[0];
    const int*   labels = (const int*)  d_in[1];
    const int*   mask   = (const int*)  d_in[2];
    const float* W1     = (const float*)d_in[3];
    const float* b1     = (const float*)d_in[4];
    const float* W2     = (const float*)d_in[5];
    const float* b2     = (const float*)d_in[6];
    const float* start  = (const float*)d_in[7];
    const float* endt   = (const float*)d_in[8];
    const float* trans  = (const float*)d_in[9];

    float* out    = (float*)d_out;
    float* logits = out + 1;   // output layout: [loss, logits(B,S,T)]

    weff_kernel<<<DD + 1, 256>>>(W1, b1, W2, b2);
    gemv_kernel<<<256, 128>>>(input, logits);
    crf_denom_kernel<<<BB, 32>>>(logits, mask, start, endt, trans);
    crf_num_kernel<<<BB, SS>>>(logits, labels, mask, start, endt, trans);
    final_kernel<<<1, BB>>>(out);
}

// round 2
// speedup vs baseline: 1.1202x; 1.1202x over previous
#include <cuda_runtime.h>
#include <cuda_bf16.h>
#include <cstdint>

#define BB 64
#define SS 512
#define DD 1024
#define HH 1024
#define TT 9
#define NC 16      // time chunks per batch
#define CL 32      // steps per chunk (t=1..511 covered)

// Scratch (device globals; no allocation allowed)
__device__ float4 g_Weff4[DD * 3];     // row d: [t0..t3][t4..t7][t8,-,-,-]
__device__ float  g_beff[TT];
__device__ float  g_P[BB * NC * 81];   // per-chunk 9x9 log-semiring composite
__device__ float  g_npart[BB * NC];    // numerator partial sums
__device__ float  g_res[BB];           // per-batch (logz - score)

// ---------------------------------------------------------------------------
// Kernel 1: Weff = W1 @ W2 (and beff = b1 @ W2 + b2).
// 129 blocks x 256 threads. W2 (36KB) staged in smem once per block; each
// warp owns one d-row, lanes split h. Block 128 handles the bias row.
// ---------------------------------------------------------------------------
__global__ __launch_bounds__(256) void weff_kernel(
    const float* __restrict__ W1, const float* __restrict__ b1,
    const float* __restrict__ W2, const float* __restrict__ b2)
{
    __shared__ float sW2[HH * TT];     // 36 KB
    int tid = threadIdx.x;
    for (int i = tid; i < HH * TT; i += 256) sW2[i] = W2[i];
    __syncthreads();

    int w = tid >> 5, l = tid & 31;
    bool isb = (blockIdx.x == DD / 8);
    if (isb && w > 0) return;
    int d = blockIdx.x * 8 + w;
    const float* src = isb ? b1 : (W1 + (size_t)d * HH);

    float acc[TT];
#pragma unroll
    for (int t = 0; t < TT; t++) acc[t] = 0.f;

    for (int h = l; h < HH; h += 32) {
        float a = src[h];
        const float* r = sW2 + h * TT;   // lane stride 9 words -> conflict-free
#pragma unroll
        for (int t = 0; t < TT; t++) acc[t] = fmaf(a, r[t], acc[t]);
    }
#pragma unroll
    for (int t = 0; t < TT; t++)
#pragma unroll
        for (int o = 16; o; o >>= 1)
            acc[t] += __shfl_xor_sync(0xffffffffu, acc[t], o);

    if (l == 0) {
        if (isb) {
#pragma unroll
            for (int t = 0; t < TT; t++) g_beff[t] = acc[t] + b2[t];
        } else {
            g_Weff4[d * 3 + 0] = make_float4(acc[0], acc[1], acc[2], acc[3]);
            g_Weff4[d * 3 + 1] = make_float4(acc[4], acc[5], acc[6], acc[7]);
            g_Weff4[d * 3 + 2] = make_float4(acc[8], 0.f, 0.f, 0.f);
        }
    }
}

// ---------------------------------------------------------------------------
// Kernel 2: logits[r,t] = sum_d input[r,d]*Weff[d,t] + beff[t].
// 256 blocks x 128 threads, one row per thread. Full Weff (48KB) resident in
// smem (broadcast reads); input streamed directly from global (coalesced via
// L1: 32 lanes hit 32 distinct 128B lines, each reused 8x). HBM-bound ~22us.
// ---------------------------------------------------------------------------
__global__ __launch_bounds__(128) void gemv_kernel(
    const float* __restrict__ input, float* __restrict__ logits)
{
    __shared__ float4 sW[DD * 3];      // 48 KB
    int tid = threadIdx.x;
    for (int i = tid; i < DD * 3; i += 128) sW[i] = g_Weff4[i];
    __syncthreads();

    int row = blockIdx.x * 128 + tid;
    const float4* in4 = (const float4*)input + (size_t)row * (DD / 4);

    float a0=0.f,a1=0.f,a2=0.f,a3=0.f,a4=0.f,a5=0.f,a6=0.f,a7=0.f,a8=0.f;

    for (int k4 = 0; k4 < DD / 4; k4 += 4) {
        float4 xb[4];
#pragma unroll
        for (int u = 0; u < 4; u++) xb[u] = in4[k4 + u];   // 4 LDG.128 in flight
#pragma unroll
        for (int u = 0; u < 4; u++) {
            int dim0 = (k4 + u) * 4;
#pragma unroll
            for (int j = 0; j < 4; j++) {
                int dim = dim0 + j;
                float4 w0 = sW[dim * 3 + 0];
                float4 w1 = sW[dim * 3 + 1];
                float4 w2 = sW[dim * 3 + 2];
                float xv = (j == 0) ? xb[u].x : (j == 1) ? xb[u].y
                         : (j == 2) ? xb[u].z : xb[u].w;
                a0 = fmaf(xv, w0.x, a0); a1 = fmaf(xv, w0.y, a1);
                a2 = fmaf(xv, w0.z, a2); a3 = fmaf(xv, w0.w, a3);
                a4 = fmaf(xv, w1.x, a4); a5 = fmaf(xv, w1.y, a5);
                a6 = fmaf(xv, w1.z, a6); a7 = fmaf(xv, w1.w, a7);
                a8 = fmaf(xv, w2.x, a8);
            }
        }
    }
    float* o = logits + (size_t)row * TT;
    o[0] = a0 + g_beff[0]; o[1] = a1 + g_beff[1]; o[2] = a2 + g_beff[2];
    o[3] = a3 + g_beff[3]; o[4] = a4 + g_beff[4]; o[5] = a5 + g_beff[5];
    o[6] = a6 + g_beff[6]; o[7] = a7 + g_beff[7]; o[8] = a8 + g_beff[8];
}

// ---------------------------------------------------------------------------
// Kernel 3: per-(batch,chunk) 9x9 log-semiring composite transition matrix,
// computed in the LINEAR domain with per-row rescaling every 8 steps
// (1 exp/step instead of 18 MUFU/step). Also computes the numerator partial
// for this chunk's time range. grid (4,64) x 128 thr, one warp per chunk.
// Lanes 0..8 own matrix column j; R[i] = R[i][lane].
// ---------------------------------------------------------------------------
__global__ __launch_bounds__(128) void crf_chunk_kernel(
    const float* __restrict__ logits, const int* __restrict__ labels,
    const int* __restrict__ mask, const float* __restrict__ trans)
{
    __shared__ float s_em[4][CL * TT];
    __shared__ int   s_mk[4][CL];

    int b = blockIdx.y;
    int w = threadIdx.x >> 5, l = threadIdx.x & 31;
    int c = blockIdx.x * 4 + w;
    int t0 = 1 + c * CL;
    int nst = min(CL, SS - t0);        // 32, except last chunk = 31

    const float* emb = logits + ((size_t)b * SS + t0) * TT;
    for (int i = l; i < nst * TT; i += 32) s_em[w][i] = emb[i];
    const int* mkb = mask + (size_t)b * SS;
    for (int i = l; i < nst; i += 32) s_mk[w][i] = mkb[t0 + i];
    __syncwarp();

    // --- numerator partial: lane l handles t = t0 + l ---
    float contrib = 0.f;
    if (l < nst) {
        int t = t0 + l;
        int mkv = s_mk[w][l];
        if (mkv != 0) {
            int tagt = labels[(size_t)b * SS + t];
            int tp = t - 1;
            while (tp > 0 && mkb[tp] == 0) tp--;
            int tagp = labels[(size_t)b * SS + tp];
            contrib = (float)mkv * (trans[tagp * TT + tagt] + s_em[w][l * TT + tagt]);
        }
    }
#pragma unroll
    for (int o = 16; o; o >>= 1) contrib += __shfl_xor_sync(0xffffffffu, contrib, o);
    if (l == 0) g_npart[b * NC + c] = contrib;

    // --- matrix chain (linear domain, scaled) ---
    bool act = (l < TT);
    float E[TT];
#pragma unroll
    for (int k = 0; k < TT; k++) E[k] = act ? __expf(trans[k * TT + l]) : 0.f;

    float R[TT], Ms[TT];
#pragma unroll
    for (int i = 0; i < TT; i++) { R[i] = (act && i == l) ? 1.f : 0.f; Ms[i] = 0.f; }

    for (int s = 0; s < nst; s++) {
        if (s_mk[w][s] != 0) {
            float eem = act ? __expf(s_em[w][s * TT + l]) : 0.f;
#pragma unroll
            for (int i = 0; i < TT; i++) {
                float p = R[i];
                float sum = 0.f;
#pragma unroll
                for (int k = 0; k < TT; k++)
                    sum = fmaf(__shfl_sync(0xffffffffu, p, k), E[k], sum);
                R[i] = sum * eem;
            }
        }
        if ((s & 7) == 7) {            // renorm (rows stay in fp32 range)
#pragma unroll
            for (int i = 0; i < TT; i++) {
                float m = R[i];
#pragma unroll
                for (int o = 8; o; o >>= 1)
                    m = fmaxf(m, __shfl_xor_sync(0xffffffffu, m, o));
                float r = __fdividef(1.f, m);
                R[i] *= r;
                Ms[i] += __logf(m);
            }
        }
    }
    if (act) {
        float* Pp = g_P + ((size_t)b * NC + c) * 81;
#pragma unroll
        for (int i = 0; i < TT; i++) Pp[i * TT + l] = Ms[i] + __logf(R[i]);
    }
}

// ---------------------------------------------------------------------------
// Kernel 4: per-batch combine: alpha0 (x) P_0 (x) ... (x) P_15, then logz,
// then final score assembly (partials + start/end terms) -> g_res[b].
// 64 blocks x 32 threads. Columns double-buffered.
// ---------------------------------------------------------------------------
__global__ __launch_bounds__(32) void crf_combine_kernel(
    const float* __restrict__ logits, const int* __restrict__ labels,
    const int* __restrict__ mask, const float* __restrict__ start,
    const float* __restrict__ endt)
{
    int b = blockIdx.x, j = threadIdx.x;
    bool act = (j < TT);
    const float NEG = -1e30f;

    float alpha = act ? (start[j] + logits[(size_t)b * SS * TT + j]) : NEG;

    const float* Pb = g_P + (size_t)b * NC * 81;
    float Pcur[TT];
#pragma unroll
    for (int i = 0; i < TT; i++) Pcur[i] = act ? Pb[i * TT + j] : NEG;

    for (int c = 0; c < NC; c++) {
        float Pn[TT];
        if (c + 1 < NC) {
#pragma unroll
            for (int i = 0; i < TT; i++)
                Pn[i] = act ? Pb[(c + 1) * 81 + i * TT + j] : NEG;
        }
        float Mp = Pcur[0];
#pragma unroll
        for (int i = 1; i < TT; i++) Mp = fmaxf(Mp, Pcur[i]);   // column max (finite: diag)
        float Ma = alpha;
#pragma unroll
        for (int o = 8; o; o >>= 1) Ma = fmaxf(Ma, __shfl_xor_sync(0xffffffffu, Ma, o));
        float q = __expf(alpha - Ma);
        float ssum = 0.f;
#pragma unroll
        for (int i = 0; i < TT; i++) {
            float qi = __shfl_sync(0xffffffffu, q, i);
            ssum = fmaf(qi, __expf(Pcur[i] - Mp), ssum);
        }
        if (act) alpha = Ma + Mp + __logf(ssum);
        if (c + 1 < NC) {
#pragma unroll
            for (int i = 0; i < TT; i++) Pcur[i] = Pn[i];
        }
    }

    // logz
    float v = act ? (alpha + endt[j]) : NEG;
    float Mx = v;
#pragma unroll
    for (int o = 8; o; o >>= 1) Mx = fmaxf(Mx, __shfl_xor_sync(0xffffffffu, Mx, o));
    float e = __expf(v - Mx);
#pragma unroll
    for (int o = 8; o; o >>= 1) e += __shfl_xor_sync(0xffffffffu, e, o);
    float logz = Mx + __logf(e);

    // numerator: sum chunk partials (fixed order butterfly)
    float np = (j < NC) ? g_npart[b * NC + j] : 0.f;
#pragma unroll
    for (int o = 16; o; o >>= 1) np += __shfl_xor_sync(0xffffffffu, np, o);

    // last masked index in [1, 511] (default 0)
    const int* mk = mask + (size_t)b * SS;
    int last = 0;
    for (int base = SS - 32; base >= 0; base -= 32) {
        int tt = base + j;
        bool mm = (tt >= 1) && (mk[tt] > 0);
        unsigned bal = __ballot_sync(0xffffffffu, mm);
        if (bal) { last = base + (31 - __clz(bal)); break; }
    }

    if (j == 0) {
        int tg0 = labels[(size_t)b * SS];
        float sc = np + start[tg0] + logits[(size_t)b * SS * TT + tg0]
                 + endt[labels[(size_t)b * SS + last]];
        g_res[b] = logz - sc;
    }
}

// ---------------------------------------------------------------------------
// Kernel 5: loss = mean(logz - score), fixed-order reduce
// ---------------------------------------------------------------------------
__global__ __launch_bounds__(64) void final_kernel(float* __restrict__ out)
{
    __shared__ float sv[BB];
    int t = threadIdx.x;
    sv[t] = g_res[t];
    __syncthreads();
#pragma unroll
    for (int o = 32; o; o >>= 1) {
        if (t < o) sv[t] += sv[t + o];
        __syncthreads();
    }
    if (t == 0) out[0] = sv[0] * (1.0f / 64.0f);
}

// ---------------------------------------------------------------------------
extern "C" void kernel_launch(void* const* d_in, const int* in_sizes, int n_in,
                              void* d_out, int out_size)
{
    const float* input  = (const float*)d_in[0];
    const int*   labels = (const int*)  d_in[1];
    const int*   mask   = (const int*)  d_in[2];
    const float* W1     = (const float*)d_in[3];
    const float* b1     = (const float*)d_in[4];
    const float* W2     = (const float*)d_in[5];
    const float* b2     = (const float*)d_in[6];
    const float* start  = (const float*)d_in[7];
    const float* endt   = (const float*)d_in[8];
    const float* trans  = (const float*)d_in[9];

    float* out    = (float*)d_out;
    float* logits = out + 1;   // output layout: [loss, logits(B,S,T)]

    weff_kernel<<<DD / 8 + 1, 256>>>(W1, b1, W2, b2);
    gemv_kernel<<<256, 128>>>(input, logits);
    crf_chunk_kernel<<<dim3(4, BB), 128>>>(logits, labels, mask, trans);
    crf_combine_kernel<<<BB, 32>>>(logits, labels, mask, start, endt);
    final_kernel<<<1, BB>>>(out);
}